// round 14
// baseline (speedup 1.0000x reference)
#include <cuda_runtime.h>
#include <cstdint>

// CRF loss forward, B=512, N=1024, K=64, sm_100a.
// 8 chains per 256-thread block: warps w and w+4 share SMSP (w&3), giving
// 2 co-resident chains per scheduler to hide the ~295-cyc step latency
// behind the ~150-slot issue stream. Per warp: linear-domain scan,
// register-resident exp(trans), f32x2 FMAs, cp.async emit ring (4 x 4-step
// buffers), emit/ex2/vote pipelined one step ahead, branch-free score
// gather, EXACT lane-0 power-of-2 lazy renorm every 4 steps (integer ctot).

typedef unsigned long long ull;
#define FULLMASK 0xffffffffu

__device__ __forceinline__ void fma2(ull &d, ull a, ull b) {
    asm("fma.rn.f32x2 %0, %1, %2, %0;" : "+l"(d) : "l"(a), "l"(b));
}
__device__ __forceinline__ ull pack2(float x, float y) {
    ull r; asm("mov.b64 %0, {%1, %2};" : "=l"(r) : "f"(x), "f"(y)); return r;
}
__device__ __forceinline__ void unpack2(ull v, float &x, float &y) {
    asm("mov.b64 {%0, %1}, %2;" : "=f"(x), "=f"(y) : "l"(v));
}
__device__ __forceinline__ float ex2f(float x) {
    float r; asm("ex2.approx.f32 %0, %1;" : "=f"(r) : "f"(x)); return r;
}
__device__ __forceinline__ float lg2f(float x) {
    float r; asm("lg2.approx.f32 %0, %1;" : "=f"(r) : "f"(x)); return r;
}
__device__ __forceinline__ float warp_maxf(float x) {
    #pragma unroll
    for (int o = 16; o; o >>= 1) x = fmaxf(x, __shfl_xor_sync(FULLMASK, x, o));
    return x;
}
__device__ __forceinline__ uint32_t s2u(const void* p) {
    uint32_t a;
    asm("{ .reg .u64 t; cvta.to.shared.u64 t, %1; cvt.u32.u64 %0, t; }"
        : "=r"(a) : "l"(p));
    return a;
}
__device__ __forceinline__ void cp16(uint32_t dst, const void* src) {
    asm volatile("cp.async.cg.shared.global [%0], [%1], 16;"
                 :: "r"(dst), "l"(src));
}
#define CP_COMMIT() asm volatile("cp.async.commit_group;")

__global__ __launch_bounds__(256) void crf_fwd_kernel(
    const float* __restrict__ y_pred,   // [B, N, K]
    const float* __restrict__ trans,    // [K, K]
    const int*   __restrict__ y_true,   // [B, N]
    float*       __restrict__ out)      // [B]
{
    constexpr int N = 1024;
    constexpr int K = 64;
    constexpr float LOG2E = 1.4426950408889634f;

    const int tid  = threadIdx.x;
    const int w    = tid >> 5;          // warp 0..7 -> SMSP (w & 3), 2 warps each
    const int lane = tid & 31;
    const int b    = blockIdx.x * 8 + w;
    const int j0   = 2 * lane, j1 = j0 + 1;

    __shared__ __align__(16) float sh_em[8][4 * 256];  // per-warp 4-buf x 4-step ring (4KB)
    __shared__ ull sh_a[8][2][32];                     // per-warp double-buffered alpha

    const float* emrow_f = y_pred + (size_t)b * N * K;
    const int*   ytrow   = y_true + (size_t)b * N;
    const uint32_t em_u32 = s2u(sh_em[w]);

    // issue one 4-step (1KB) emit group into ring buffer (GP&3)
    #define PREFETCH(GP)                                                       \
    {                                                                          \
        int bt = (GP) * 4; if (bt > N - 4) bt = N - 4;                         \
        const char* src = (const char*)(emrow_f + (size_t)bt * K) + lane * 16; \
        uint32_t dst = em_u32 + (uint32_t)(((GP) & 3) * 1024) + lane * 16;     \
        cp16(dst,       src);                                                  \
        cp16(dst + 512, src + 512);                                            \
        CP_COMMIT();                                                           \
    }

    PREFETCH(0)
    PREFETCH(1)

    // ---- E = exp(trans) columns j0, j1 in registers (overlaps cp.async) ----
    ull Er0[32], Er1[32];
    #pragma unroll
    for (int p = 0; p < 32; p++) {
        float t00 = __ldg(&trans[(2 * p)     * K + j0]);
        float t01 = __ldg(&trans[(2 * p + 1) * K + j0]);
        float t10 = __ldg(&trans[(2 * p)     * K + j1]);
        float t11 = __ldg(&trans[(2 * p + 1) * K + j1]);
        Er0[p] = pack2(ex2f(t00 * LOG2E), ex2f(t01 * LOG2E));
        Er1[p] = pack2(ex2f(t10 * LOG2E), ex2f(t11 * LOG2E));
    }

    asm volatile("cp.async.wait_group 1;");   // group 0 resident
    __syncwarp();

    // ---- t = 0 init (from ring slot 0) ----
    float  pt = 0.f;
    float  mx0;
    int    ctot = 0;     // exact power-of-2 scale accumulator (log2 units)
    int    ytprev, ytcur;
    bool   pm;
    float  s0p, s1p;
    {
        float2 v = *(const float2*)(sh_em[w] + 2 * lane);
        bool okl = (v.x > -1e6f) & (v.y > -1e6f);
        bool ok0 = __all_sync(FULLMASK, okl);
        float mv0 = ok0 ? v.x : 0.f;
        float mv1 = ok0 ? v.y : 0.f;
        float mx = warp_maxf(fmaxf(mv0, mv1));
        s0p = ex2f((mv0 - mx) * LOG2E);
        s1p = ex2f((mv1 - mx) * LOG2E);
        mx0 = mx;
        ytprev = __ldg(&ytrow[0]);
        ytcur  = __ldg(&ytrow[1]);
        if (ok0 && (ytprev >> 1) == lane) pt += (ytprev & 1) ? v.y : v.x;
        pm = ok0;
        sh_a[w][0][lane] = pack2(s0p, s1p);
    }
    __syncwarp();

    // ---- prime the one-step-ahead emit pipeline for t = 1 (slot 1) ----
    float2 em_c = *(const float2*)(sh_em[w] + 64 + 2 * lane);
    float  e0c  = ex2f(em_c.x * LOG2E);
    float  e1c  = ex2f(em_c.y * LOG2E);
    bool   okc  = __all_sync(FULLMASK, (em_c.x > -1e6f) & (em_c.y > -1e6f));

    float pendinv = 1.0f;   // exact pow-2 deferred scale
    int   buf = 0;

    // one scan step; TT/KK compile-time; RENORM compile-time.
    // uses pipelined em_c/e0c/e1c/okc, prefetches slot KK+1 for next step.
    #define STEP(TT, KK, RENORM)                                               \
    {                                                                          \
        const float* nb = ((KK) == 3) ? ebase_next : ebase;                    \
        float2 em_n = *(const float2*)(nb + (((KK) + 1) & 3) * 64 + 2 * lane); \
        float e0n = ex2f(em_n.x * LOG2E);                                      \
        float e1n = ex2f(em_n.y * LOG2E);                                      \
        bool  okn = __all_sync(FULLMASK, (em_n.x > -1e6f) & (em_n.y > -1e6f)); \
        int yt = ytcur;                                                        \
        ytcur = __ldg(&ytrow[((TT) + 1 > N - 1) ? (N - 1) : (TT) + 1]);        \
        float trv = __ldg(&trans[ytprev * K + yt]);                            \
        float e0 = e0c * pendinv;                                              \
        float e1 = e1c * pendinv;                                              \
        const ulonglong2* ap = (const ulonglong2*)sh_a[w][buf];                \
        ull A0 = 0ull, A1 = 0ull, B0 = 0ull, B1 = 0ull;                        \
        _Pragma("unroll")                                                      \
        for (int q = 0; q < 8; q++) {                                          \
            ulonglong2 v0 = ap[2 * q];                                         \
            ulonglong2 v1 = ap[2 * q + 1];                                     \
            fma2(A0, v0.x, Er0[4 * q]);                                        \
            fma2(B0, v0.x, Er1[4 * q]);                                        \
            fma2(A1, v0.y, Er0[4 * q + 1]);                                    \
            fma2(B1, v0.y, Er1[4 * q + 1]);                                    \
            fma2(A0, v1.x, Er0[4 * q + 2]);                                    \
            fma2(B0, v1.x, Er1[4 * q + 2]);                                    \
            fma2(A1, v1.y, Er0[4 * q + 3]);                                    \
            fma2(B1, v1.y, Er1[4 * q + 3]);                                    \
        }                                                                      \
        float xa, ya, xb, yb, xc, yc, xd, yd;                                  \
        unpack2(A0, xa, ya); unpack2(A1, xb, yb);                              \
        unpack2(B0, xc, yc); unpack2(B1, xd, yd);                              \
        float s0n = (((xa + xb) + (ya + yb))) * e0;                            \
        float s1n = (((xc + xd) + (yc + yd))) * e1;                            \
        float s0 = okc ? s0n : s0p;                                            \
        float s1 = okc ? s1n : s1p;                                            \
        pendinv = okc ? 1.0f : pendinv;                                        \
        bool match = ((yt >> 1) == lane) & okc;                                \
        float femit = (yt & 1) ? em_c.y : em_c.x;                              \
        float tadd  = pm ? trv : 0.0f;                                         \
        pt += match ? (femit + tadd) : 0.0f;                                   \
        pm = okc; ytprev = yt;                                                 \
        s0p = s0; s1p = s1;                                                    \
        sh_a[w][buf ^ 1][lane] = pack2(s0, s1);                                \
        buf ^= 1;                                                              \
        em_c = em_n; e0c = e0n; e1c = e1n; okc = okn;                          \
        __syncwarp();                                                          \
        if (RENORM) {                                                          \
            float r = __shfl_sync(FULLMASK, s0, 0);                            \
            int be = (__float_as_int(r) >> 23) & 0xff;                         \
            be = (be < 1) ? 127 : ((be > 253) ? 253 : be);                     \
            pendinv *= __int_as_float((254 - be) << 23);                       \
            ctot += be - 127;                                                  \
        }                                                                      \
    }

    // ---- group 0: t = 1..3 (buffer 0 resident) ----
    {
        PREFETCH(2)
        asm volatile("cp.async.wait_group 1;");
        __syncwarp();
        const float* ebase      = sh_em[w];
        const float* ebase_next = sh_em[w] + 256;
        STEP(1, 1, false)
        STEP(2, 2, false)
        STEP(3, 3, false)
    }

    // ---- groups 1..255: t = 4G..4G+3; renorm at t % 4 == 0 (first step) ----
    for (int G = 1; G < 256; G++) {
        PREFETCH(G + 2)
        asm volatile("cp.async.wait_group 1;");
        __syncwarp();
        const float* ebase      = sh_em[w] + (G & 3) * 256;
        const float* ebase_next = sh_em[w] + ((G + 1) & 3) * 256;
        const int t0 = G * 4;
        STEP(t0 + 0, 0, true)
        STEP(t0 + 1, 1, false)
        STEP(t0 + 2, 2, false)
        STEP(t0 + 3, 3, false)
    }
    #undef STEP
    #undef PREFETCH

    // ---- finalize: apply unconsumed pending scale, reduce, output ----
    float ssum = (s0p + s1p) * pendinv;
    #pragma unroll
    for (int o = 16; o; o >>= 1) {
        ssum += __shfl_xor_sync(FULLMASK, ssum, o);
        pt   += __shfl_xor_sync(FULLMASK, pt,   o);
    }
    if (lane == 0) {
        double log2norm = (double)mx0 * 1.4426950408889634
                        + (double)ctot + (double)lg2f(ssum);
        out[b] = (float)(log2norm * 0.6931471805599453 - (double)pt);
    }
}

extern "C" void kernel_launch(void* const* d_in, const int* in_sizes, int n_in,
                              void* d_out, int out_size) {
    const float* y_pred = (const float*)d_in[0];
    const float* trans  = (const float*)d_in[1];
    const int*   y_true = (const int*)d_in[2];
    float* out = (float*)d_out;

    const int B = in_sizes[2] / 1024;   // 512
    crf_fwd_kernel<<<B / 8, 256>>>(y_pred, trans, y_true, out);
}